// round 14
// baseline (speedup 1.0000x reference)
#include <cuda_runtime.h>
#include <stdint.h>

#define B_ 4
#define V_ 778
#define F_ 1538
#define S_ 320
#define TILE 16
#define NT 64          // 64 threads; each thread: 4 vertically-adjacent pixels
#define NW (NT / 32)
#define NSPLIT 16
#define SFACES ((F_ + NSPLIT - 1) / NSPLIT)   // 97 faces per split

// Per (batch, face): 3 edges x (A', B', C', pad) with NEGATED scaled coeffs:
// dn = A'*px + B'*py + C' = -(dist/sigma)*log2(e);  t = exp2(dn) = exp(-dist/sigma).
__device__ float g_coeffs[B_ * F_ * 12];
// partial products per split: [split][b][y][x]
__device__ float g_part[NSPLIT * B_ * S_ * S_];

__global__ void precompute_kernel(const float* __restrict__ verts,
                                  const int* __restrict__ faces) {
    int idx = blockIdx.x * blockDim.x + threadIdx.x;
    if (idx >= B_ * F_) return;
    int b = idx / F_;
    int f = idx - b * F_;
    int i0 = faces[f * 3 + 0], i1 = faces[f * 3 + 1], i2 = faces[f * 3 + 2];
    const float* vb = verts + b * V_ * 3;
    float x0 = vb[i0 * 3 + 0], y0 = -vb[i0 * 3 + 1];
    float x1 = vb[i1 * 3 + 0], y1 = -vb[i1 * 3 + 1];
    float x2 = vb[i2 * 3 + 0], y2 = -vb[i2 * 3 + 1];
    float area2 = (x1 - x0) * (y2 - y0) - (y1 - y0) * (x2 - x0);
    float sgn = (area2 > 0.f) ? 1.f : ((area2 < 0.f) ? -1.f : 0.f);
    const float INVS = 1.4426950408889634f / 0.01f;  // log2(e)/SIGMA

    float ax[3] = {x0, x1, x2}, ay[3] = {y0, y1, y2};
    float bx[3] = {x1, x2, x0}, by[3] = {y1, y2, y0};
    float* o = g_coeffs + idx * 12;
#pragma unroll
    for (int e = 0; e < 3; e++) {
        float ex = bx[e] - ax[e];
        float ey = by[e] - ay[e];
        float inv_len = 1.0f / (sqrtf(ex * ex + ey * ey) + 1e-8f);
        float k = sgn * inv_len * INVS;
        // negated coefficients
        o[e * 4 + 0] = k * ey;
        o[e * 4 + 1] = -k * ex;
        o[e * 4 + 2] = k * (ex * ay[e] - ey * ax[e]);
        o[e * 4 + 3] = 0.f;
    }
}

__device__ __forceinline__ float ex2f(float x) {
    float r; asm("ex2.approx.ftz.f32 %0, %1;" : "=f"(r) : "f"(x)); return r;
}
__device__ __forceinline__ float rcpf(float x) {
    float r; asm("rcp.approx.ftz.f32 %0, %1;" : "=f"(r) : "f"(x)); return r;
}

// classify + accumulate one pixel given negated edge distances
__device__ __forceinline__ void acc_pixel(float dn0, float dn1, float dn2,
                                          float L, float DPN, float RMIN,
                                          float& W) {
    float mx01 = fmaxf(dn0, dn1);
    float m = fmaxf(mx01, dn2);
    if (m < L) {
        float r;
        if (m < DPN) {
            r = RMIN;                       // all edges deep: clipped const
        } else {
            float mn01 = fminf(dn0, dn1);
            float mid = fmaxf(mn01, fminf(mx01, dn2));
            if (mid < DPN) {
                float t = ex2f(m);          // single relevant edge
                r = fmaxf(t * rcpf(1.0f + t), RMIN);
            } else {
                float t0 = ex2f(dn0);
                float t1 = ex2f(dn1);
                float t2 = ex2f(dn2);
                float sA = t1 + t2;
                float pA = t1 * t2;
                float sp = sA + pA;
                float Q = fmaf(t0, sp, t0 + sp);
                r = fmaxf(Q * rcpf(1.0f + Q), RMIN);
            }
        }
        W *= r;
    }
}

__global__ __launch_bounds__(NT) void silhouette_kernel() {
    __shared__ float4 s_face[SFACES * 3];   // compacted (e0,e1,e2) per active face
    __shared__ int s_wcnt[NW];
    __shared__ int s_wbase[NW];
    __shared__ int s_total;
    __shared__ int s_deep;

    const int tid = threadIdx.x;
    const int w = tid >> 5;
    const int lane = tid & 31;
    const int bz = blockIdx.z;          // b*NSPLIT + split
    const int b = bz >> 4;
    const int split = bz & 15;
    const int x0 = blockIdx.x * TILE;
    const int y0 = blockIdx.y * TILE;

    // thresholds on dn = -(dist/sigma)*log2(e)
    const float L = 8.6561702f;        // 6*log2e : live if max(dn) < L
    const float DPN = -21.6404256f;    // -15*log2e : dn < DPN means edge deep
    const float STEP = 2.0f / S_;

    const float cx = (x0 + 8.0f) * STEP - 1.0f;
    const float cy = (y0 + 8.0f) * STEP - 1.0f;
    const float hx = 7.5f * STEP + 1e-4f;
    const float hy = hx;

    // this thread's 4 pixels: column xi, rows 4*yp .. 4*yp+3
    const int xi = tid & 15;
    const int yp = tid >> 4;                 // 0..3
    const int pxi = x0 + xi;
    const int ry = y0 + 4 * yp;
    const float px = (pxi + 0.5f) * STEP - 1.0f;
    const float py0 = (ry + 0.5f) * STEP - 1.0f;

    const float RMIN = 1.0f - (1.0f - 1e-6f);   // exact fp32 clip residue
    float W0 = 1.0f, W1 = 1.0f, W2 = 1.0f, W3 = 1.0f;

    const float* cb = g_coeffs + (size_t)b * F_ * 12;
    const int fLo = split * SFACES;
    const int fHi = min(fLo + SFACES, F_);

    if (tid == 0) { s_deep = 0; s_total = 0; }
    __syncthreads();

    // ---- cull: chunks of NT faces, accumulating compaction ----
    for (int base = fLo; base < fHi; base += NT) {
        int f = base + tid;
        bool active = false, deep = false;
        float4 e0, e1, e2;
        if (f < fHi) {
            const float4* cp = (const float4*)(cb + (size_t)f * 12);
            e0 = __ldg(cp); e1 = __ldg(cp + 1); e2 = __ldg(cp + 2);
            float n0 = fmaf(e0.x, cx, fmaf(e0.y, cy, e0.z));
            float n1 = fmaf(e1.x, cx, fmaf(e1.y, cy, e1.z));
            float n2 = fmaf(e2.x, cx, fmaf(e2.y, cy, e2.z));
            float x0e = fmaf(fabsf(e0.x), hx, fabsf(e0.y) * hy);
            float x1e = fmaf(fabsf(e1.x), hx, fabsf(e1.y) * hy);
            float x2e = fmaf(fabsf(e2.x), hx, fabsf(e2.y) * hy);
            bool dead = (n0 - x0e > L) || (n1 - x1e > L) || (n2 - x2e > L);
            deep = (n0 + x0e < DPN) && (n1 + x1e < DPN) && (n2 + x2e < DPN);
            active = !dead && !deep;
        }
        unsigned balA = __ballot_sync(0xffffffffu, active);
        unsigned balD = __ballot_sync(0xffffffffu, deep);
        if (lane == 0) s_wcnt[w] = __popc(balA);
        __syncthreads();
        if (tid == 0) {   // deterministic exclusive scan, accumulating
            int acc = s_total;
#pragma unroll
            for (int i = 0; i < NW; i++) { s_wbase[i] = acc; acc += s_wcnt[i]; }
            s_total = acc;
        }
        if (lane == 0 && balD) atomicAdd(&s_deep, __popc(balD));
        __syncthreads();
        if (active) {
            int pos = s_wbase[w] + __popc(balA & ((1u << lane) - 1u));
            s_face[pos * 3 + 0] = e0;
            s_face[pos * 3 + 1] = e1;
            s_face[pos * 3 + 2] = e2;
        }
        __syncthreads();
    }

    // ---- eval: 4 vertically-adjacent pixels per thread ----
    const int n = s_total;
    const float4* sp_ = s_face;
#pragma unroll 2
    for (int j = 0; j < n; j++, sp_ += 3) {
        float4 f0 = sp_[0];
        float4 f1 = sp_[1];
        float4 f2 = sp_[2];
        float st0 = f0.y * STEP, st1 = f1.y * STEP, st2 = f2.y * STEP;
        // row0 distances
        float a0 = fmaf(f0.y, py0, fmaf(f0.x, px, f0.z));
        float a1 = fmaf(f1.y, py0, fmaf(f1.x, px, f1.z));
        float a2 = fmaf(f2.y, py0, fmaf(f2.x, px, f2.z));
        acc_pixel(a0, a1, a2, L, DPN, RMIN, W0);
        float b0 = a0 + st0, b1 = a1 + st1, b2 = a2 + st2;
        acc_pixel(b0, b1, b2, L, DPN, RMIN, W1);
        float c0 = b0 + st0, c1 = b1 + st1, c2 = b2 + st2;
        acc_pixel(c0, c1, c2, L, DPN, RMIN, W2);
        float d0 = c0 + st0, d1 = c1 + st1, d2 = c2 + st2;
        acc_pixel(d0, d1, d2, L, DPN, RMIN, W3);
    }

    // fold deep faces of this split: exact clipped constant per face
    int nd = s_deep;
    if (nd >= 8) {
        W0 = W1 = W2 = W3 = 0.0f;
    } else {
        for (int i = 0; i < nd; i++) { W0 *= RMIN; W1 *= RMIN; W2 *= RMIN; W3 *= RMIN; }
    }

    float* op = g_part + (((size_t)split * B_ + b) * S_ + ry) * S_ + pxi;
    op[0] = W0;
    op[S_] = W1;
    op[2 * S_] = W2;
    op[3 * S_] = W3;
}

__global__ __launch_bounds__(256) void combine_kernel(float* __restrict__ out) {
    int i = blockIdx.x * blockDim.x + threadIdx.x;
    const int N4 = B_ * S_ * S_ / 4;
    if (i >= N4) return;
    const float4* gp = (const float4*)g_part;
    float4 w = gp[i];
#pragma unroll
    for (int s = 1; s < NSPLIT; s++) {
        float4 p = gp[s * N4 + i];
        w.x *= p.x; w.y *= p.y; w.z *= p.z; w.w *= p.w;
    }
    ((float4*)out)[i] = make_float4(1.0f - w.x, 1.0f - w.y, 1.0f - w.z, 1.0f - w.w);
}

extern "C" void kernel_launch(void* const* d_in, const int* in_sizes, int n_in,
                              void* d_out, int out_size) {
    const float* verts = (const float*)d_in[0];
    const int* faces = (const int*)d_in[1];
    float* out = (float*)d_out;

    int total = B_ * F_;
    precompute_kernel<<<(total + 255) / 256, 256>>>(verts, faces);

    dim3 grid(S_ / TILE, S_ / TILE, B_ * NSPLIT);
    silhouette_kernel<<<grid, NT>>>();

    int n4 = B_ * S_ * S_ / 4;
    combine_kernel<<<(n4 + 255) / 256, 256>>>(out);
}

// round 15
// speedup vs baseline: 1.0244x; 1.0244x over previous
#include <cuda_runtime.h>
#include <stdint.h>

#define B_ 4
#define V_ 778
#define F_ 1538
#define S_ 320
#define TILE 16
#define NT 128         // 128 threads; each thread: 2 vertically-adjacent pixels
#define NW (NT / 32)
#define NSPLIT 8
#define SFACES ((F_ + NSPLIT - 1) / NSPLIT)   // 193 faces per split -> 2 cull chunks

// Per (batch, face): 3 edges x (A', B', C', pad) with NEGATED scaled coeffs:
// dn = A'*px + B'*py + C' = -(dist/sigma)*log2(e);  t = exp2(dn) = exp(-dist/sigma).
__device__ float g_coeffs[B_ * F_ * 12];
// partial products per split: [split][b][y][x]
__device__ float g_part[NSPLIT * B_ * S_ * S_];

__global__ void precompute_kernel(const float* __restrict__ verts,
                                  const int* __restrict__ faces) {
    int idx = blockIdx.x * blockDim.x + threadIdx.x;
    if (idx >= B_ * F_) return;
    int b = idx / F_;
    int f = idx - b * F_;
    int i0 = faces[f * 3 + 0], i1 = faces[f * 3 + 1], i2 = faces[f * 3 + 2];
    const float* vb = verts + b * V_ * 3;
    float x0 = vb[i0 * 3 + 0], y0 = -vb[i0 * 3 + 1];
    float x1 = vb[i1 * 3 + 0], y1 = -vb[i1 * 3 + 1];
    float x2 = vb[i2 * 3 + 0], y2 = -vb[i2 * 3 + 1];
    float area2 = (x1 - x0) * (y2 - y0) - (y1 - y0) * (x2 - x0);
    float sgn = (area2 > 0.f) ? 1.f : ((area2 < 0.f) ? -1.f : 0.f);
    const float INVS = 1.4426950408889634f / 0.01f;  // log2(e)/SIGMA

    float ax[3] = {x0, x1, x2}, ay[3] = {y0, y1, y2};
    float bx[3] = {x1, x2, x0}, by[3] = {y1, y2, y0};
    float* o = g_coeffs + idx * 12;
#pragma unroll
    for (int e = 0; e < 3; e++) {
        float ex = bx[e] - ax[e];
        float ey = by[e] - ay[e];
        float inv_len = 1.0f / (sqrtf(ex * ex + ey * ey) + 1e-8f);
        float k = sgn * inv_len * INVS;
        // negated coefficients
        o[e * 4 + 0] = k * ey;
        o[e * 4 + 1] = -k * ex;
        o[e * 4 + 2] = k * (ex * ay[e] - ey * ax[e]);
        o[e * 4 + 3] = 0.f;
    }
}

__device__ __forceinline__ float ex2f(float x) {
    float r; asm("ex2.approx.ftz.f32 %0, %1;" : "=f"(r) : "f"(x)); return r;
}
__device__ __forceinline__ float rcpf(float x) {
    float r; asm("rcp.approx.ftz.f32 %0, %1;" : "=f"(r) : "f"(x)); return r;
}

// classify + accumulate one pixel given negated edge distances
__device__ __forceinline__ void acc_pixel(float dn0, float dn1, float dn2,
                                          float L, float DPN, float RMIN,
                                          float& W) {
    float mx01 = fmaxf(dn0, dn1);
    float m = fmaxf(mx01, dn2);
    if (m < L) {
        float r;
        if (m < DPN) {
            r = RMIN;                       // all edges deep: clipped const
        } else {
            float mn01 = fminf(dn0, dn1);
            float mid = fmaxf(mn01, fminf(mx01, dn2));
            if (mid < DPN) {
                float t = ex2f(m);          // single relevant edge
                r = fmaxf(t * rcpf(1.0f + t), RMIN);
            } else {
                float t0 = ex2f(dn0);
                float t1 = ex2f(dn1);
                float t2 = ex2f(dn2);
                float sA = t1 + t2;
                float pA = t1 * t2;
                float sp = sA + pA;
                float Q = fmaf(t0, sp, t0 + sp);
                r = fmaxf(Q * rcpf(1.0f + Q), RMIN);
            }
        }
        W *= r;
    }
}

__global__ __launch_bounds__(NT) void silhouette_kernel() {
    __shared__ float4 s_face[SFACES * 3];   // compacted (e0,e1,e2) per active face
    __shared__ int s_wcnt[NW];
    __shared__ int s_wbase[NW];
    __shared__ int s_total;
    __shared__ int s_deep;

    const int tid = threadIdx.x;
    const int w = tid >> 5;
    const int lane = tid & 31;
    const int bz = blockIdx.z;          // b*NSPLIT + split
    const int b = bz >> 3;
    const int split = bz & 7;
    const int x0 = blockIdx.x * TILE;
    const int y0 = blockIdx.y * TILE;

    // thresholds on dn = -(dist/sigma)*log2(e)
    const float L = 8.6561702f;        // 6*log2e : live if max(dn) < L
    const float DPN = -21.6404256f;    // -15*log2e : dn < DPN means edge deep
    const float STEP = 2.0f / S_;

    const float cx = (x0 + 8.0f) * STEP - 1.0f;
    const float cy = (y0 + 8.0f) * STEP - 1.0f;
    const float hx = 7.5f * STEP + 1e-4f;
    const float hy = hx;

    // this thread's 2 pixels: column xi, rows 2*yp and 2*yp+1
    const int xi = tid & 15;
    const int yp = tid >> 4;                 // 0..7
    const int pxi = x0 + xi;
    const int ry = y0 + 2 * yp;
    const float px = (pxi + 0.5f) * STEP - 1.0f;
    const float py0 = (ry + 0.5f) * STEP - 1.0f;

    const float RMIN = 1.0f - (1.0f - 1e-6f);   // exact fp32 clip residue
    float WA = 1.0f, WB = 1.0f;

    const float* cb = g_coeffs + (size_t)b * F_ * 12;
    const int fLo = split * SFACES;
    const int fHi = min(fLo + SFACES, F_);

    if (tid == 0) { s_deep = 0; s_total = 0; }
    __syncthreads();

    // ---- cull: chunks of NT faces, accumulating compaction ----
    for (int base = fLo; base < fHi; base += NT) {
        int f = base + tid;
        bool active = false, deep = false;
        float4 e0, e1, e2;
        if (f < fHi) {
            const float4* cp = (const float4*)(cb + (size_t)f * 12);
            e0 = __ldg(cp); e1 = __ldg(cp + 1); e2 = __ldg(cp + 2);
            float n0 = fmaf(e0.x, cx, fmaf(e0.y, cy, e0.z));
            float n1 = fmaf(e1.x, cx, fmaf(e1.y, cy, e1.z));
            float n2 = fmaf(e2.x, cx, fmaf(e2.y, cy, e2.z));
            float x0e = fmaf(fabsf(e0.x), hx, fabsf(e0.y) * hy);
            float x1e = fmaf(fabsf(e1.x), hx, fabsf(e1.y) * hy);
            float x2e = fmaf(fabsf(e2.x), hx, fabsf(e2.y) * hy);
            // dead: whole tile beyond L on some edge (dn - ext > L)
            bool dead = (n0 - x0e > L) || (n1 - x1e > L) || (n2 - x2e > L);
            // deep: whole tile deep inside all edges (dn + ext < DPN)
            deep = (n0 + x0e < DPN) && (n1 + x1e < DPN) && (n2 + x2e < DPN);
            active = !dead && !deep;
        }
        unsigned balA = __ballot_sync(0xffffffffu, active);
        unsigned balD = __ballot_sync(0xffffffffu, deep);
        if (lane == 0) s_wcnt[w] = __popc(balA);
        __syncthreads();
        if (tid == 0) {   // deterministic exclusive scan, accumulating
            int acc = s_total;
#pragma unroll
            for (int i = 0; i < NW; i++) { s_wbase[i] = acc; acc += s_wcnt[i]; }
            s_total = acc;
        }
        if (lane == 0 && balD) atomicAdd(&s_deep, __popc(balD));
        __syncthreads();
        if (active) {
            int pos = s_wbase[w] + __popc(balA & ((1u << lane) - 1u));
            s_face[pos * 3 + 0] = e0;
            s_face[pos * 3 + 1] = e1;
            s_face[pos * 3 + 2] = e2;
        }
        __syncthreads();
    }

    // ---- eval: 2 vertically-adjacent pixels per thread ----
    const int n = s_total;
    const float4* sp_ = s_face;
#pragma unroll 2
    for (int j = 0; j < n; j++, sp_ += 3) {
        float4 f0 = sp_[0];
        float4 f1 = sp_[1];
        float4 f2 = sp_[2];
        // row0 distances
        float a0 = fmaf(f0.y, py0, fmaf(f0.x, px, f0.z));
        float a1 = fmaf(f1.y, py0, fmaf(f1.x, px, f1.z));
        float a2 = fmaf(f2.y, py0, fmaf(f2.x, px, f2.z));
        // row1 = row0 + B'*STEP (incremental)
        float b0 = fmaf(f0.y, STEP, a0);
        float b1 = fmaf(f1.y, STEP, a1);
        float b2 = fmaf(f2.y, STEP, a2);

        acc_pixel(a0, a1, a2, L, DPN, RMIN, WA);
        acc_pixel(b0, b1, b2, L, DPN, RMIN, WB);
    }

    // fold deep faces of this split: exact clipped constant per face
    int nd = s_deep;
    if (nd >= 8) {
        WA = 0.0f; WB = 0.0f;
    } else {
        for (int i = 0; i < nd; i++) { WA *= RMIN; WB *= RMIN; }
    }

    float* op = g_part + (((size_t)split * B_ + b) * S_ + ry) * S_ + pxi;
    op[0] = WA;
    op[S_] = WB;
}

__global__ __launch_bounds__(256) void combine_kernel(float* __restrict__ out) {
    int i = blockIdx.x * blockDim.x + threadIdx.x;
    const int N4 = B_ * S_ * S_ / 4;
    if (i >= N4) return;
    const float4* gp = (const float4*)g_part;
    float4 w = gp[i];
#pragma unroll
    for (int s = 1; s < NSPLIT; s++) {
        float4 p = gp[s * N4 + i];
        w.x *= p.x; w.y *= p.y; w.z *= p.z; w.w *= p.w;
    }
    ((float4*)out)[i] = make_float4(1.0f - w.x, 1.0f - w.y, 1.0f - w.z, 1.0f - w.w);
}

extern "C" void kernel_launch(void* const* d_in, const int* in_sizes, int n_in,
                              void* d_out, int out_size) {
    const float* verts = (const float*)d_in[0];
    const int* faces = (const int*)d_in[1];
    float* out = (float*)d_out;

    int total = B_ * F_;
    precompute_kernel<<<(total + 255) / 256, 256>>>(verts, faces);

    dim3 grid(S_ / TILE, S_ / TILE, B_ * NSPLIT);
    silhouette_kernel<<<grid, NT>>>();

    int n4 = B_ * S_ * S_ / 4;
    combine_kernel<<<(n4 + 255) / 256, 256>>>(out);
}

// round 16
// speedup vs baseline: 1.1502x; 1.1228x over previous
#include <cuda_runtime.h>
#include <stdint.h>

#define B_ 4
#define V_ 778
#define F_ 1538
#define S_ 320
#define TILE 16
#define NT 128         // 128 threads; each thread: 2 vertically-adjacent pixels
#define NW (NT / 32)
#define NSPLIT 16
#define SFACES ((F_ + NSPLIT - 1) / NSPLIT)   // 97 <= NT : single cull chunk

// Per (batch, face): 3 edges x (A', B', C', pad) with NEGATED scaled coeffs:
// dn = A'*px + B'*py + C' = -(dist/sigma)*log2(e);  t = exp2(dn) = exp(-dist/sigma).
__device__ float g_coeffs[B_ * F_ * 12];
// partial products per split: [split][b][y][x]
__device__ float g_part[NSPLIT * B_ * S_ * S_];

__global__ void precompute_kernel(const float* __restrict__ verts,
                                  const int* __restrict__ faces) {
    int idx = blockIdx.x * blockDim.x + threadIdx.x;
    if (idx >= B_ * F_) return;
    int b = idx / F_;
    int f = idx - b * F_;
    int i0 = faces[f * 3 + 0], i1 = faces[f * 3 + 1], i2 = faces[f * 3 + 2];
    const float* vb = verts + b * V_ * 3;
    float x0 = vb[i0 * 3 + 0], y0 = -vb[i0 * 3 + 1];
    float x1 = vb[i1 * 3 + 0], y1 = -vb[i1 * 3 + 1];
    float x2 = vb[i2 * 3 + 0], y2 = -vb[i2 * 3 + 1];
    float area2 = (x1 - x0) * (y2 - y0) - (y1 - y0) * (x2 - x0);
    float sgn = (area2 > 0.f) ? 1.f : ((area2 < 0.f) ? -1.f : 0.f);
    const float INVS = 1.4426950408889634f / 0.01f;  // log2(e)/SIGMA

    float ax[3] = {x0, x1, x2}, ay[3] = {y0, y1, y2};
    float bx[3] = {x1, x2, x0}, by[3] = {y1, y2, y0};
    float* o = g_coeffs + idx * 12;
#pragma unroll
    for (int e = 0; e < 3; e++) {
        float ex = bx[e] - ax[e];
        float ey = by[e] - ay[e];
        float inv_len = 1.0f / (sqrtf(ex * ex + ey * ey) + 1e-8f);
        float k = sgn * inv_len * INVS;
        // negated coefficients
        o[e * 4 + 0] = k * ey;
        o[e * 4 + 1] = -k * ex;
        o[e * 4 + 2] = k * (ex * ay[e] - ey * ax[e]);
        o[e * 4 + 3] = 0.f;
    }
}

__device__ __forceinline__ float ex2f(float x) {
    float r; asm("ex2.approx.ftz.f32 %0, %1;" : "=f"(r) : "f"(x)); return r;
}
__device__ __forceinline__ float rcpf(float x) {
    float r; asm("rcp.approx.ftz.f32 %0, %1;" : "=f"(r) : "f"(x)); return r;
}

// classify + accumulate one pixel given negated edge distances
// two-class: single relevant edge (covers fully-deep via underflow) vs full.
__device__ __forceinline__ void acc_pixel(float dn0, float dn1, float dn2,
                                          float L, float DPN, float RMIN,
                                          float& W) {
    float mx01 = fmaxf(dn0, dn1);
    float m = fmaxf(mx01, dn2);
    if (m < L) {
        float r;
        float mn01 = fminf(dn0, dn1);
        float mid = fmaxf(mn01, fminf(mx01, dn2));
        if (mid < DPN) {
            // other edges negligible; for m < DPN too, t underflows -> r = RMIN
            float t = ex2f(m);
            r = fmaxf(t * rcpf(1.0f + t), RMIN);
        } else {
            float t0 = ex2f(dn0);
            float t1 = ex2f(dn1);
            float t2 = ex2f(dn2);
            float sA = t1 + t2;
            float pA = t1 * t2;
            float sp = sA + pA;
            float Q = fmaf(t0, sp, t0 + sp);
            r = fmaxf(Q * rcpf(1.0f + Q), RMIN);
        }
        W *= r;
    }
}

__global__ __launch_bounds__(NT) void silhouette_kernel() {
    __shared__ float4 s_face[SFACES * 3];   // compacted (e0,e1,e2) per active face
    __shared__ int s_wcnt[NW];
    __shared__ int s_wbase[NW];
    __shared__ int s_total;
    __shared__ int s_deep;

    const int tid = threadIdx.x;
    const int w = tid >> 5;
    const int lane = tid & 31;
    const int bz = blockIdx.z;          // b*NSPLIT + split
    const int b = bz >> 4;
    const int split = bz & 15;
    const int x0 = blockIdx.x * TILE;
    const int y0 = blockIdx.y * TILE;

    // thresholds on dn = -(dist/sigma)*log2(e)
    const float L = 8.6561702f;        // 6*log2e : live if max(dn) < L
    const float DPN = -21.6404256f;    // -15*log2e : dn < DPN means edge deep
    const float STEP = 2.0f / S_;

    const float cx = (x0 + 8.0f) * STEP - 1.0f;
    const float cy = (y0 + 8.0f) * STEP - 1.0f;
    const float hx = 7.5f * STEP + 1e-4f;
    const float hy = hx;

    // this thread's 2 pixels: column xi, rows 2*yp and 2*yp+1
    const int xi = tid & 15;
    const int yp = tid >> 4;                 // 0..7
    const int pxi = x0 + xi;
    const int ry = y0 + 2 * yp;
    const float px = (pxi + 0.5f) * STEP - 1.0f;
    const float py0 = (ry + 0.5f) * STEP - 1.0f;

    const float RMIN = 1.0f - (1.0f - 1e-6f);   // exact fp32 clip residue
    float WA = 1.0f, WB = 1.0f;

    const float* cb = g_coeffs + (size_t)b * F_ * 12;
    const int fLo = split * SFACES;
    const int fHi = min(fLo + SFACES, F_);

    // ---- cull (single chunk: SFACES <= NT): one face per thread ----
    {
        int f = fLo + tid;
        bool active = false, deep = false;
        float4 e0, e1, e2;
        if (f < fHi) {
            const float4* cp = (const float4*)(cb + (size_t)f * 12);
            e0 = __ldg(cp); e1 = __ldg(cp + 1); e2 = __ldg(cp + 2);
            float n0 = fmaf(e0.x, cx, fmaf(e0.y, cy, e0.z));
            float n1 = fmaf(e1.x, cx, fmaf(e1.y, cy, e1.z));
            float n2 = fmaf(e2.x, cx, fmaf(e2.y, cy, e2.z));
            float x0e = fmaf(fabsf(e0.x), hx, fabsf(e0.y) * hy);
            float x1e = fmaf(fabsf(e1.x), hx, fabsf(e1.y) * hy);
            float x2e = fmaf(fabsf(e2.x), hx, fabsf(e2.y) * hy);
            // dead: whole tile beyond L on some edge (dn - ext > L)
            bool dead = (n0 - x0e > L) || (n1 - x1e > L) || (n2 - x2e > L);
            // deep: whole tile deep inside all edges (dn + ext < DPN)
            deep = (n0 + x0e < DPN) && (n1 + x1e < DPN) && (n2 + x2e < DPN);
            active = !dead && !deep;
        }
        unsigned balA = __ballot_sync(0xffffffffu, active);
        unsigned balD = __ballot_sync(0xffffffffu, deep);
        if (lane == 0) {
            s_wcnt[w] = __popc(balA);
            if (w == 0) s_deep = 0;
        }
        __syncthreads();
        if (tid == 0) {   // deterministic exclusive scan
            int acc = 0;
#pragma unroll
            for (int i = 0; i < NW; i++) { s_wbase[i] = acc; acc += s_wcnt[i]; }
            s_total = acc;
        }
        if (lane == 0 && balD) atomicAdd(&s_deep, __popc(balD));
        __syncthreads();
        if (active) {
            int pos = s_wbase[w] + __popc(balA & ((1u << lane) - 1u));
            s_face[pos * 3 + 0] = e0;
            s_face[pos * 3 + 1] = e1;
            s_face[pos * 3 + 2] = e2;
        }
        __syncthreads();
    }

    // ---- eval: 2 vertically-adjacent pixels per thread ----
    const int n = s_total;
    const float4* sp_ = s_face;
#pragma unroll 2
    for (int j = 0; j < n; j++, sp_ += 3) {
        float4 f0 = sp_[0];
        float4 f1 = sp_[1];
        float4 f2 = sp_[2];
        // row0 distances
        float a0 = fmaf(f0.y, py0, fmaf(f0.x, px, f0.z));
        float a1 = fmaf(f1.y, py0, fmaf(f1.x, px, f1.z));
        float a2 = fmaf(f2.y, py0, fmaf(f2.x, px, f2.z));
        // row1 = row0 + B'*STEP (incremental)
        float b0 = fmaf(f0.y, STEP, a0);
        float b1 = fmaf(f1.y, STEP, a1);
        float b2 = fmaf(f2.y, STEP, a2);

        acc_pixel(a0, a1, a2, L, DPN, RMIN, WA);
        acc_pixel(b0, b1, b2, L, DPN, RMIN, WB);
    }

    // fold deep faces of this split: exact clipped constant per face
    int nd = s_deep;
    if (nd >= 8) {
        WA = 0.0f; WB = 0.0f;
    } else {
        for (int i = 0; i < nd; i++) { WA *= RMIN; WB *= RMIN; }
    }

    float* op = g_part + (((size_t)split * B_ + b) * S_ + ry) * S_ + pxi;
    op[0] = WA;
    op[S_] = WB;
}

__global__ __launch_bounds__(256) void combine_kernel(float* __restrict__ out) {
    int i = blockIdx.x * blockDim.x + threadIdx.x;
    const int N4 = B_ * S_ * S_ / 4;
    if (i >= N4) return;
    const float4* gp = (const float4*)g_part;
    float4 w = gp[i];
#pragma unroll
    for (int s = 1; s < NSPLIT; s++) {
        float4 p = gp[s * N4 + i];
        w.x *= p.x; w.y *= p.y; w.z *= p.z; w.w *= p.w;
    }
    ((float4*)out)[i] = make_float4(1.0f - w.x, 1.0f - w.y, 1.0f - w.z, 1.0f - w.w);
}

extern "C" void kernel_launch(void* const* d_in, const int* in_sizes, int n_in,
                              void* d_out, int out_size) {
    const float* verts = (const float*)d_in[0];
    const int* faces = (const int*)d_in[1];
    float* out = (float*)d_out;

    int total = B_ * F_;                         // 6152
    precompute_kernel<<<(total + 127) / 128, 128>>>(verts, faces);

    dim3 grid(S_ / TILE, S_ / TILE, B_ * NSPLIT);
    silhouette_kernel<<<grid, NT>>>();

    int n4 = B_ * S_ * S_ / 4;
    combine_kernel<<<(n4 + 255) / 256, 256>>>(out);
}